// round 4
// baseline (speedup 1.0000x reference)
#include <cuda_runtime.h>

#define PP    35
#define CIN   7
#define C1    16
#define A1C   32
#define C2    64
#define A2C   128
#define C3    128
#define DD    10
#define HH    200
#define WWG   176
#define VMAX  20000
#define NBUCK 64
#define NCH   (C1 + C2 + C3)   // 208
#define NP1   20               // padded pair count for vfe1 (18 real)
#define T2    160              // vfe2 threads (5 warps)
#define GRID2 296              // 2 CTAs/SM * 148

typedef unsigned long long ull;

// ---------------- scratch ---------------------------------------------------------
__device__ float  g_h2[(size_t)VMAX * PP * C2];    // pre-BN h2
__device__ float  g_keep[(size_t)VMAX * PP];
__device__ float  g_max3[(size_t)VMAX * C3];
__device__ float  g_min3[(size_t)VMAX * C3];
__device__ double g_sumB [NBUCK][NCH];
__device__ double g_sqB  [NBUCK][NCH];
__device__ float  g_scale[NCH];
__device__ float  g_shift[NCH];

// ---------------- f32x2 helpers ----------------------------------------------------
__device__ __forceinline__ ull pack2(float lo, float hi) {
    ull r;
    asm("mov.b64 %0, {%1, %2};" : "=l"(r) : "f"(lo), "f"(hi));
    return r;
}
__device__ __forceinline__ float2 unpack2(ull v) {
    float2 r;
    asm("mov.b64 {%0, %1}, %2;" : "=f"(r.x), "=f"(r.y) : "l"(v));
    return r;
}
__device__ __forceinline__ void fma2(ull& d, ull a, ull b) {
    asm("fma.rn.f32x2 %0, %1, %2, %0;" : "+l"(d) : "l"(a), "l"(b));
}

// ---------------- zero stat buckets ------------------------------------------------
__global__ void k_zero_stats() {
    int n = NBUCK * NCH;
    for (int i = blockIdx.x * blockDim.x + threadIdx.x; i < n; i += gridDim.x * blockDim.x) {
        ((double*)g_sumB)[i] = 0.0;
        ((double*)g_sqB)[i]  = 0.0;
    }
}

// ---------------- pass 1: stats of h1 ---------------------------------------------
__global__ void k_stats1(const float* __restrict__ x,
                         const float* __restrict__ W1,
                         const float* __restrict__ b1, int V) {
    int N = V * PP;
    float lsum[C1], lsq[C1];
    #pragma unroll
    for (int u = 0; u < C1; u++) { lsum[u] = 0.f; lsq[u] = 0.f; }
    for (int r = blockIdx.x * blockDim.x + threadIdx.x; r < N; r += gridDim.x * blockDim.x) {
        float xv[CIN];
        #pragma unroll
        for (int c = 0; c < CIN; c++) xv[c] = x[(size_t)r * CIN + c];
        #pragma unroll
        for (int u = 0; u < C1; u++) {
            float h = b1[u];
            #pragma unroll
            for (int c = 0; c < CIN; c++) h = fmaf(xv[c], W1[c * C1 + u], h);
            lsum[u] += h; lsq[u] += h * h;
        }
    }
    __shared__ float ssum[C1], ssq[C1];
    if (threadIdx.x < C1) { ssum[threadIdx.x] = 0.f; ssq[threadIdx.x] = 0.f; }
    __syncthreads();
    #pragma unroll
    for (int u = 0; u < C1; u++) { atomicAdd(&ssum[u], lsum[u]); atomicAdd(&ssq[u], lsq[u]); }
    __syncthreads();
    if (threadIdx.x < C1) {
        int b = blockIdx.x & (NBUCK - 1);
        atomicAdd(&g_sumB[b][threadIdx.x], (double)ssum[threadIdx.x]);
        atomicAdd(&g_sqB [b][threadIdx.x], (double)ssq [threadIdx.x]);
    }
}

// ---------------- finalize BN params -----------------------------------------------
__global__ void k_finalize(const float* __restrict__ g, const float* __restrict__ be,
                           int off, int nc, double invN) {
    int u = threadIdx.x;
    if (u < nc) {
        double s = 0.0, q = 0.0;
        for (int b = 0; b < NBUCK; b++) { s += g_sumB[b][off + u]; q += g_sqB[b][off + u]; }
        double m   = s * invN;
        double var = q * invN - m * m;
        float  sc  = g[u] * rsqrtf((float)var + 1e-5f);
        g_scale[off + u] = sc;
        g_shift[off + u] = (float)((double)be[u] - m * (double)sc);
    }
}

// ---------------- pass 2: BN1+relu, max, concat; packed h2 GEMM -> g_h2 -----------
__global__ void __launch_bounds__(128) k_vfe1(const float* __restrict__ x,
                       const float* __restrict__ W1, const float* __restrict__ b1,
                       const float* __restrict__ W2, const float* __restrict__ b2, int V) {
    int v = blockIdx.x;
    if (v >= V) return;
    int t = threadIdx.x;

    __shared__ float  s_x[PP * CIN];
    __shared__ float  s_keep[PP + 1];
    __shared__ float  s_h1[PP * C1];
    __shared__ float  s_m1[C1];
    __shared__ float2 s_a1p[A1C * NP1];
    __shared__ float  s_w2[A1C * C2];
    __shared__ float  s_rs[4 * C2], s_rq[4 * C2];

    const float* xb = x + (size_t)v * (PP * CIN);
    for (int i = t; i < PP * CIN; i += 128) s_x[i] = xb[i];
    for (int i = t; i < A1C * C2; i += 128) s_w2[i] = W2[i];
    __syncthreads();

    if (t < PP) {
        float s = 0.f;
        #pragma unroll
        for (int c = 0; c < CIN; c++) s += s_x[t * CIN + c];
        float k = (s != 0.0f) ? 1.0f : 0.0f;
        s_keep[t] = k;
        g_keep[(size_t)v * PP + t] = k;
    }
    __syncthreads();

    for (int i = t; i < PP * C1; i += 128) {
        int p = i >> 4, u = i & 15;
        float h = b1[u];
        #pragma unroll
        for (int c = 0; c < CIN; c++) h = fmaf(s_x[p * CIN + c], W1[c * C1 + u], h);
        h = fmaf(h, g_scale[u], g_shift[u]);
        s_h1[i] = fmaxf(h, 0.0f);
    }
    __syncthreads();

    if (t < C1) {
        float m = s_h1[t];
        #pragma unroll 7
        for (int p = 1; p < PP; p++) m = fmaxf(m, s_h1[p * C1 + t]);
        s_m1[t] = m;
    }
    __syncthreads();

    for (int i = t; i < A1C * NP1; i += 128) {
        int k = i / NP1, pr = i % NP1;
        int p0 = 2 * pr, p1 = p0 + 1;
        float u0 = 0.f, u1 = 0.f;
        if (p0 < PP) u0 = (k < C1 ? s_h1[p0 * C1 + k] : s_m1[k - C1]) * s_keep[p0];
        if (p1 < PP) u1 = (k < C1 ? s_h1[p1 * C1 + k] : s_m1[k - C1]) * s_keep[p1];
        s_a1p[i] = make_float2(u0, u1);
    }
    __syncthreads();

    int lane = t & 31, pg = t >> 5;
    int og = lane * 2;
    float b0 = b2[og], b1v = b2[og + 1];
    ull acc[5][2];
    #pragma unroll
    for (int n = 0; n < 5; n++) { acc[n][0] = pack2(b0, b0); acc[n][1] = pack2(b1v, b1v); }

    #pragma unroll 4
    for (int k = 0; k < A1C; k++) {
        float2 w = *(const float2*)&s_w2[k * C2 + og];
        ull w0 = pack2(w.x, w.x), w1 = pack2(w.y, w.y);
        const ull* ap = (const ull*)&s_a1p[k * NP1 + pg * 5];
        #pragma unroll
        for (int n = 0; n < 5; n++) {
            ull a = ap[n];
            fma2(acc[n][0], a, w0);
            fma2(acc[n][1], a, w1);
        }
    }

    float ls0 = 0.f, lq0 = 0.f, ls1 = 0.f, lq1 = 0.f;
    float* h2g = g_h2 + (size_t)v * (PP * C2);
    #pragma unroll
    for (int n = 0; n < 5; n++) {
        int pr = pg * 5 + n;
        if (pr < 18) {
            int p0 = 2 * pr, p1 = p0 + 1;
            float2 r0 = unpack2(acc[n][0]);
            float2 r1 = unpack2(acc[n][1]);
            *(float2*)&h2g[p0 * C2 + og] = make_float2(r0.x, r1.x);
            ls0 += r0.x; lq0 += r0.x * r0.x;
            ls1 += r1.x; lq1 += r1.x * r1.x;
            if (p1 < PP) {
                *(float2*)&h2g[p1 * C2 + og] = make_float2(r0.y, r1.y);
                ls0 += r0.y; lq0 += r0.y * r0.y;
                ls1 += r1.y; lq1 += r1.y * r1.y;
            }
        }
    }
    s_rs[pg * C2 + og] = ls0; s_rs[pg * C2 + og + 1] = ls1;
    s_rq[pg * C2 + og] = lq0; s_rq[pg * C2 + og + 1] = lq1;
    __syncthreads();
    if (t < C2) {
        float S = s_rs[t] + s_rs[C2 + t] + s_rs[2 * C2 + t] + s_rs[3 * C2 + t];
        float Q = s_rq[t] + s_rq[C2 + t] + s_rq[2 * C2 + t] + s_rq[3 * C2 + t];
        int b = v & (NBUCK - 1);
        atomicAdd(&g_sumB[b][C1 + t], (double)S);
        atomicAdd(&g_sqB [b][C1 + t], (double)Q);
    }
}

// ---------------- pass 3: persistent; output-packed FFMA2 GEMM --------------------
// smem (floats after 64KB of s_wd):
//   s_hb  [36][68]   (keep-folded after max)
//   s_h3  [35][132]
//   s_m2  [64], s_mm [2][64], s_keep[40], s_sc[64], s_sh[64]
#define HB_STRIDE 68
#define H3_STRIDE 132
#define OFF_HB    0
#define OFF_H3    (OFF_HB + 36 * HB_STRIDE)
#define OFF_M2    (OFF_H3 + 35 * H3_STRIDE)
#define OFF_MM    (OFF_M2 + 64)
#define OFF_KEEP  (OFF_MM + 128)
#define OFF_SC    (OFF_KEEP + 40)
#define OFF_SH    (OFF_SC + 64)
#define OFF_END   (OFF_SH + 64)
#define SM2_BYTES (65536 + OFF_END * 4)

__global__ void __launch_bounds__(T2, 2) k_vfe2(const float4* __restrict__ Wd4,
                                                const float*  __restrict__ bd, int V) {
    extern __shared__ char sm2[];
    float* s_wd   = (float*)sm2;                       // [128][128]
    float* s_base = (float*)(sm2 + 65536);
    float* s_hb   = s_base + OFF_HB;
    float* s_h3   = s_base + OFF_H3;
    float* s_m2   = s_base + OFF_M2;
    float* s_mm   = s_base + OFF_MM;
    float* s_keep = s_base + OFF_KEEP;
    float* s_sc   = s_base + OFF_SC;
    float* s_sh   = s_base + OFF_SH;

    int t = threadIdx.x;
    int ogi = t & 7;           // 0..7 -> 16 outputs each
    int pg  = t >> 3;          // 0..19 -> 2 points each
    int og  = ogi * 16;
    int p0  = 2 * pg, p1 = p0 + 1;

    // stage Wd + BN2 params once
    for (int i = t; i < (A2C * A2C) / 4; i += T2) ((float4*)s_wd)[i] = Wd4[i];
    if (t < C2) { s_sc[t] = g_scale[C1 + t]; s_sh[t] = g_shift[C1 + t]; }
    // zero pad rows of s_hb (p = 35)
    for (int i = t; i < HB_STRIDE; i += T2) s_hb[35 * HB_STRIDE + i] = 0.f;
    __syncthreads();

    ull bq[8];
    #pragma unroll
    for (int j = 0; j < 8; j++) bq[j] = ((const ull*)bd)[og / 2 + j];

    for (int v = blockIdx.x; v < V; v += gridDim.x) {
        if (t < 40) s_keep[t] = (t < PP) ? g_keep[(size_t)v * PP + t] : 0.f;

        // h2 load + BN2 + relu -> s_hb (pre-keep)
        const float4* h2g4 = (const float4*)(g_h2 + (size_t)v * (PP * C2));
        for (int i = t; i < (PP * C2) / 4; i += T2) {
            float4 h = h2g4[i];
            int p = i >> 4, u = (i & 15) * 4;
            h.x = fmaxf(fmaf(h.x, s_sc[u],     s_sh[u]),     0.f);
            h.y = fmaxf(fmaf(h.y, s_sc[u + 1], s_sh[u + 1]), 0.f);
            h.z = fmaxf(fmaf(h.z, s_sc[u + 2], s_sh[u + 2]), 0.f);
            h.w = fmaxf(fmaf(h.w, s_sc[u + 3], s_sh[u + 3]), 0.f);
            ((float4*)(s_hb + p * HB_STRIDE))[(i & 15)] = h;
        }
        __syncthreads();

        // partial column max (two halves of P)
        if (t < 128) {
            int ch = t & 63, half = t >> 6;
            int pb = half * 18, pe = half ? PP : 18;
            float m = -3.4e38f;
            for (int p = pb; p < pe; p++) m = fmaxf(m, s_hb[p * HB_STRIDE + ch]);
            s_mm[half * 64 + ch] = m;
        }
        __syncthreads();

        // combine max + fold keep into s_hb in place
        if (t < C2) s_m2[t] = fmaxf(s_mm[t], s_mm[64 + t]);
        for (int i = t; i < PP * C2; i += T2) {
            int p = i >> 6, u = i & 63;
            s_hb[p * HB_STRIDE + u] *= s_keep[p];
        }
        __syncthreads();

        // GEMM: thread = 16 outputs (8 packed pairs) x 2 points
        float kp0 = s_keep[p0], kp1 = s_keep[p1];
        ull acc0[8], acc1[8];
        #pragma unroll
        for (int j = 0; j < 8; j++) { acc0[j] = bq[j]; acc1[j] = bq[j]; }

        const float* hb0 = s_hb + p0 * HB_STRIDE;
        const float* hb1 = s_hb + p1 * HB_STRIDE;

        #pragma unroll 4
        for (int k = 0; k < 64; k++) {
            const ull* wp = (const ull*)(s_wd + k * A2C + og);
            float a0f = hb0[k], a1f = hb1[k];
            ull a0 = pack2(a0f, a0f), a1 = pack2(a1f, a1f);
            #pragma unroll
            for (int j = 0; j < 8; j++) {
                fma2(acc0[j], a0, wp[j]);
                fma2(acc1[j], a1, wp[j]);
            }
        }
        #pragma unroll 4
        for (int k = 64; k < 128; k++) {
            const ull* wp = (const ull*)(s_wd + k * A2C + og);
            float m = s_m2[k - 64];
            float a0f = m * kp0, a1f = m * kp1;
            ull a0 = pack2(a0f, a0f), a1 = pack2(a1f, a1f);
            #pragma unroll
            for (int j = 0; j < 8; j++) {
                fma2(acc0[j], a0, wp[j]);
                fma2(acc1[j], a1, wp[j]);
            }
        }

        // write pre-BN h3 tile (real points only)
        if (p0 < PP) {
            ull* dst = (ull*)(s_h3 + p0 * H3_STRIDE + og);
            #pragma unroll
            for (int j = 0; j < 8; j++) dst[j] = acc0[j];
        }
        if (p1 < PP) {
            ull* dst = (ull*)(s_h3 + p1 * H3_STRIDE + og);
            #pragma unroll
            for (int j = 0; j < 8; j++) dst[j] = acc1[j];
        }
        __syncthreads();

        // per-channel stats + max/min over 35 points
        if (t < C3) {
            float S = 0.f, Q = 0.f, MX = -3.4e38f, MN = 3.4e38f;
            #pragma unroll 7
            for (int p = 0; p < PP; p++) {
                float val = s_h3[p * H3_STRIDE + t];
                S += val; Q = fmaf(val, val, Q);
                MX = fmaxf(MX, val); MN = fminf(MN, val);
            }
            g_max3[(size_t)v * C3 + t] = MX;
            g_min3[(size_t)v * C3 + t] = MN;
            int b = v & (NBUCK - 1);
            atomicAdd(&g_sumB[b][C1 + C2 + t], (double)S);
            atomicAdd(&g_sqB [b][C1 + C2 + t], (double)Q);
        }
        __syncthreads();
    }
}

// ---------------- pass 4: BN3 + relu + max (via max/min) + scatter-add ------------
__global__ void k_scatter(const int* __restrict__ coord, float* __restrict__ out, int V) {
    int v = blockIdx.x;
    if (v >= V) return;
    int u = threadIdx.x;
    float sc = g_scale[C1 + C2 + u];
    float sh = g_shift[C1 + C2 + u];
    float h  = (sc >= 0.0f) ? g_max3[(size_t)v * C3 + u] : g_min3[(size_t)v * C3 + u];
    float val = fmaxf(fmaf(h, sc, sh), 0.0f);
    int cz = coord[v * 3 + 0];
    int cy = coord[v * 3 + 1];
    int cx = coord[v * 3 + 2];
    size_t off = (size_t)u * (DD * HH * WWG) + (size_t)cz * (HH * WWG) + (size_t)cy * WWG + cx;
    atomicAdd(out + off, val);
}

// ---------------- launch -----------------------------------------------------------
extern "C" void kernel_launch(void* const* d_in, const int* in_sizes, int n_in,
                              void* d_out, int out_size) {
    const float* x     = (const float*)d_in[0];
    const int*   coord = (const int*)  d_in[1];
    const float* W1 = (const float*)d_in[2];
    const float* b1 = (const float*)d_in[3];
    const float* g1 = (const float*)d_in[4];
    const float* be1= (const float*)d_in[5];
    const float* W2 = (const float*)d_in[6];
    const float* b2 = (const float*)d_in[7];
    const float* g2 = (const float*)d_in[8];
    const float* be2= (const float*)d_in[9];
    const float* Wd = (const float*)d_in[10];
    const float* bd = (const float*)d_in[11];
    const float* gd = (const float*)d_in[12];
    const float* bed= (const float*)d_in[13];

    int V = in_sizes[1] / 3;
    if (V > VMAX) V = VMAX;
    double invN = 1.0 / ((double)V * PP);

    cudaFuncSetAttribute(k_vfe2, cudaFuncAttributeMaxDynamicSharedMemorySize, SM2_BYTES);

    cudaMemsetAsync(d_out, 0, (size_t)out_size * sizeof(float), 0);
    k_zero_stats<<<32, 256>>>();
    k_stats1<<<592, 256>>>(x, W1, b1, V);
    k_finalize<<<1, 256>>>(g1, be1, 0, C1, invN);
    k_vfe1<<<V, 128>>>(x, W1, b1, W2, b2, V);
    k_finalize<<<1, 256>>>(g2, be2, C1, C2, invN);
    k_vfe2<<<GRID2, T2, SM2_BYTES>>>((const float4*)Wd, bd, V);
    k_finalize<<<1, 256>>>(gd, bed, C1 + C2, C3, invN);
    k_scatter<<<V, 128>>>(coord, (float*)d_out, V);
}

// round 5
// speedup vs baseline: 3.0540x; 3.0540x over previous
#include <cuda_runtime.h>

#define PP    35
#define CIN   7
#define C1    16
#define A1C   32
#define C2    64
#define A2C   128
#define C3    128
#define DD    10
#define HH    200
#define WWG   176
#define VMAX  20000
#define NBUCK 64
#define NCH   (C1 + C2 + C3)   // 208
#define NP1   20               // padded pair count for vfe1 (18 real)
#define T2    160              // vfe2 threads (5 warps)
#define GRID2 296              // 2 CTAs/SM * 148

typedef unsigned long long ull;

// ---------------- scratch ---------------------------------------------------------
__device__ float  g_h2[(size_t)VMAX * PP * C2];    // pre-BN h2
__device__ float  g_keep[(size_t)VMAX * PP];
__device__ float  g_max3[(size_t)VMAX * C3];
__device__ float  g_min3[(size_t)VMAX * C3];
__device__ double g_sumB [NBUCK][NCH];
__device__ double g_sqB  [NBUCK][NCH];
__device__ float  g_scale[NCH];
__device__ float  g_shift[NCH];

// ---------------- f32x2 helpers ----------------------------------------------------
__device__ __forceinline__ ull pack2(float lo, float hi) {
    ull r;
    asm("mov.b64 %0, {%1, %2};" : "=l"(r) : "f"(lo), "f"(hi));
    return r;
}
__device__ __forceinline__ float2 unpack2(ull v) {
    float2 r;
    asm("mov.b64 {%0, %1}, %2;" : "=f"(r.x), "=f"(r.y) : "l"(v));
    return r;
}
__device__ __forceinline__ void fma2(ull& d, ull a, ull b) {
    asm("fma.rn.f32x2 %0, %1, %2, %0;" : "+l"(d) : "l"(a), "l"(b));
}

// ---------------- zero stat buckets ------------------------------------------------
__global__ void k_zero_stats() {
    int n = NBUCK * NCH;
    for (int i = blockIdx.x * blockDim.x + threadIdx.x; i < n; i += gridDim.x * blockDim.x) {
        ((double*)g_sumB)[i] = 0.0;
        ((double*)g_sqB)[i]  = 0.0;
    }
}

// ---------------- pass 1: stats of h1 ---------------------------------------------
__global__ void k_stats1(const float* __restrict__ x,
                         const float* __restrict__ W1,
                         const float* __restrict__ b1, int V) {
    int N = V * PP;
    float lsum[C1], lsq[C1];
    #pragma unroll
    for (int u = 0; u < C1; u++) { lsum[u] = 0.f; lsq[u] = 0.f; }
    for (int r = blockIdx.x * blockDim.x + threadIdx.x; r < N; r += gridDim.x * blockDim.x) {
        float xv[CIN];
        #pragma unroll
        for (int c = 0; c < CIN; c++) xv[c] = x[(size_t)r * CIN + c];
        #pragma unroll
        for (int u = 0; u < C1; u++) {
            float h = b1[u];
            #pragma unroll
            for (int c = 0; c < CIN; c++) h = fmaf(xv[c], W1[c * C1 + u], h);
            lsum[u] += h; lsq[u] += h * h;
        }
    }
    __shared__ float ssum[C1], ssq[C1];
    if (threadIdx.x < C1) { ssum[threadIdx.x] = 0.f; ssq[threadIdx.x] = 0.f; }
    __syncthreads();
    #pragma unroll
    for (int u = 0; u < C1; u++) { atomicAdd(&ssum[u], lsum[u]); atomicAdd(&ssq[u], lsq[u]); }
    __syncthreads();
    if (threadIdx.x < C1) {
        int b = blockIdx.x & (NBUCK - 1);
        atomicAdd(&g_sumB[b][threadIdx.x], (double)ssum[threadIdx.x]);
        atomicAdd(&g_sqB [b][threadIdx.x], (double)ssq [threadIdx.x]);
    }
}

// ---------------- finalize BN params -----------------------------------------------
__global__ void k_finalize(const float* __restrict__ g, const float* __restrict__ be,
                           int off, int nc, double invN) {
    int u = threadIdx.x;
    if (u < nc) {
        double s = 0.0, q = 0.0;
        for (int b = 0; b < NBUCK; b++) { s += g_sumB[b][off + u]; q += g_sqB[b][off + u]; }
        double m   = s * invN;
        double var = q * invN - m * m;
        float  sc  = g[u] * rsqrtf((float)var + 1e-5f);
        g_scale[off + u] = sc;
        g_shift[off + u] = (float)((double)be[u] - m * (double)sc);
    }
}

// ---------------- pass 2: BN1+relu, max; HALVED h2 GEMM -> g_h2 -------------------
// h2pre[p][o] = keep[p]*(sum_{k<16} h1[p][k]*W2[k][o] + C[o]) + b2[o]
// C[o] = sum_{k<16} m1[k]*W2[16+k][o]
__global__ void __launch_bounds__(128) k_vfe1(const float* __restrict__ x,
                       const float* __restrict__ W1, const float* __restrict__ b1,
                       const float* __restrict__ W2, const float* __restrict__ b2, int V) {
    int v = blockIdx.x;
    if (v >= V) return;
    int t = threadIdx.x;

    __shared__ float  s_x[PP * CIN];
    __shared__ float  s_keep[PP + 1];
    __shared__ float  s_h1[PP * C1];
    __shared__ float  s_m1[C1];
    __shared__ float  s_C[C2];
    __shared__ float2 s_a1p[C1 * NP1];
    __shared__ float  s_w2[A1C * C2];
    __shared__ float  s_rs[4 * C2], s_rq[4 * C2];

    const float* xb = x + (size_t)v * (PP * CIN);
    for (int i = t; i < PP * CIN; i += 128) s_x[i] = xb[i];
    for (int i = t; i < A1C * C2; i += 128) s_w2[i] = W2[i];
    __syncthreads();

    if (t < PP) {
        float s = 0.f;
        #pragma unroll
        for (int c = 0; c < CIN; c++) s += s_x[t * CIN + c];
        float k = (s != 0.0f) ? 1.0f : 0.0f;
        s_keep[t] = k;
        g_keep[(size_t)v * PP + t] = k;
    }
    __syncthreads();

    for (int i = t; i < PP * C1; i += 128) {
        int p = i >> 4, u = i & 15;
        float h = b1[u];
        #pragma unroll
        for (int c = 0; c < CIN; c++) h = fmaf(s_x[p * CIN + c], W1[c * C1 + u], h);
        h = fmaf(h, g_scale[u], g_shift[u]);
        s_h1[i] = fmaxf(h, 0.0f);
    }
    __syncthreads();

    if (t < C1) {
        float m = s_h1[t];
        #pragma unroll 7
        for (int p = 1; p < PP; p++) m = fmaxf(m, s_h1[p * C1 + t]);
        s_m1[t] = m;
    }
    __syncthreads();

    // pair buffer (lower 16 k only) + broadcast-half C[o]
    for (int i = t; i < C1 * NP1; i += 128) {
        int k = i / NP1, pr = i % NP1;
        int p0 = 2 * pr, p1 = p0 + 1;
        float u0 = 0.f, u1 = 0.f;
        if (p0 < PP) u0 = s_h1[p0 * C1 + k] * s_keep[p0];
        if (p1 < PP) u1 = s_h1[p1 * C1 + k] * s_keep[p1];
        s_a1p[i] = make_float2(u0, u1);
    }
    if (t < C2) {
        float c = 0.f;
        #pragma unroll
        for (int k = 0; k < C1; k++) c = fmaf(s_m1[k], s_w2[(C1 + k) * C2 + t], c);
        s_C[t] = c;
    }
    __syncthreads();

    // GEMM (k<16): thread = 2 outputs x 5 pairs
    int lane = t & 31, pg = t >> 5;
    int og = lane * 2;
    ull acc[5][2];
    #pragma unroll
    for (int n = 0; n < 5; n++) { acc[n][0] = 0ULL; acc[n][1] = 0ULL; }

    #pragma unroll 4
    for (int k = 0; k < C1; k++) {
        float2 w = *(const float2*)&s_w2[k * C2 + og];
        ull w0 = pack2(w.x, w.x), w1 = pack2(w.y, w.y);
        const ull* ap = (const ull*)&s_a1p[k * NP1 + pg * 5];
        #pragma unroll
        for (int n = 0; n < 5; n++) {
            ull a = ap[n];
            fma2(acc[n][0], a, w0);
            fma2(acc[n][1], a, w1);
        }
    }

    float C0 = s_C[og], C1v = s_C[og + 1];
    float b0 = b2[og],  b1s = b2[og + 1];
    float ls0 = 0.f, lq0 = 0.f, ls1 = 0.f, lq1 = 0.f;
    float* h2g = g_h2 + (size_t)v * (PP * C2);
    #pragma unroll
    for (int n = 0; n < 5; n++) {
        int pr = pg * 5 + n;
        if (pr < 18) {
            int p0 = 2 * pr, p1 = p0 + 1;
            float2 r0 = unpack2(acc[n][0]);
            float2 r1 = unpack2(acc[n][1]);
            float k0 = s_keep[p0];
            float h00 = fmaf(k0, r0.x + C0,  b0);
            float h01 = fmaf(k0, r1.x + C1v, b1s);
            *(float2*)&h2g[p0 * C2 + og] = make_float2(h00, h01);
            ls0 += h00; lq0 += h00 * h00;
            ls1 += h01; lq1 += h01 * h01;
            if (p1 < PP) {
                float k1 = s_keep[p1];
                float h10 = fmaf(k1, r0.y + C0,  b0);
                float h11 = fmaf(k1, r1.y + C1v, b1s);
                *(float2*)&h2g[p1 * C2 + og] = make_float2(h10, h11);
                ls0 += h10; lq0 += h10 * h10;
                ls1 += h11; lq1 += h11 * h11;
            }
        }
    }
    s_rs[pg * C2 + og] = ls0; s_rs[pg * C2 + og + 1] = ls1;
    s_rq[pg * C2 + og] = lq0; s_rq[pg * C2 + og + 1] = lq1;
    __syncthreads();
    if (t < C2) {
        float S = s_rs[t] + s_rs[C2 + t] + s_rs[2 * C2 + t] + s_rs[3 * C2 + t];
        float Q = s_rq[t] + s_rq[C2 + t] + s_rq[2 * C2 + t] + s_rq[3 * C2 + t];
        int b = v & (NBUCK - 1);
        atomicAdd(&g_sumB[b][C1 + t], (double)S);
        atomicAdd(&g_sqB [b][C1 + t], (double)Q);
    }
}

// ---------------- pass 3: persistent; transposed weights; halved GEMM -------------
// transposed row layout: for output o (ogi=o>>4, j=(o>>1)&7, e=o&1):
//   phys = (j>>1)*32 + ogi*4 + (j&1)*2 + e
#define HB_S  68
#define H3_S  132
#define F_HB   0
#define F_H3   (F_HB + 40 * HB_S)                 // 2720
#define F_B    (F_H3 + PP * H3_S)                 // +4620
#define F_M2   (F_B  + 128)
#define F_MM   (F_M2 + 64)
#define F_KEEP (F_MM + 128)
#define F_SC   (F_KEEP + 40)
#define F_SH   (F_SC + 64)
#define F_END  (F_SH + 64)
#define SM2_BYTES (65536 + F_END * 4)

__global__ void __launch_bounds__(T2, 2) k_vfe2(const float4* __restrict__ Wd4,
                                                const float*  __restrict__ bd, int V) {
    extern __shared__ char sm2[];
    float* s_wd   = (float*)sm2;                   // [128][128] transposed rows
    float* s_base = (float*)(sm2 + 65536);
    float* s_hb   = s_base + F_HB;
    float* s_h3   = s_base + F_H3;
    float* s_B    = s_base + F_B;
    float* s_m2   = s_base + F_M2;
    float* s_mm   = s_base + F_MM;
    float* s_keep = s_base + F_KEEP;
    float* s_sc   = s_base + F_SC;
    float* s_sh   = s_base + F_SH;

    int t = threadIdx.x;
    int ogi = t & 7;           // 16 outputs: o in [16*ogi, 16*ogi+16)
    int pg  = t >> 3;          // 0..19 -> points 2pg, 2pg+1
    int p0  = 2 * pg, p1 = p0 + 1;

    // stage Wd transposed + BN2 params; zero pad rows of s_hb
    for (int i = t; i < A2C * 32; i += T2) {
        int k = i >> 5, c = i & 31;
        float4 wv = Wd4[i];
        float* base = s_wd + k * A2C + (c & 3) * 32 + (c >> 2) * 4;
        *(ull*)(base)     = pack2(wv.x, wv.y);
        *(ull*)(base + 2) = pack2(wv.z, wv.w);
    }
    if (t < C2) { s_sc[t] = g_scale[C1 + t]; s_sh[t] = g_shift[C1 + t]; }
    for (int i = 35 * HB_S + t; i < 40 * HB_S; i += T2) s_hb[i] = 0.f;
    __syncthreads();

    for (int v = blockIdx.x; v < V; v += gridDim.x) {
        if (t < 40) s_keep[t] = (t < PP) ? g_keep[(size_t)v * PP + t] : 0.f;

        // h2 load + BN2 + relu
        const float4* h2g4 = (const float4*)(g_h2 + (size_t)v * (PP * C2));
        for (int i = t; i < (PP * C2) / 4; i += T2) {
            float4 h = h2g4[i];
            int p = i >> 4, c4 = i & 15, u = c4 * 4;
            h.x = fmaxf(fmaf(h.x, s_sc[u],     s_sh[u]),     0.f);
            h.y = fmaxf(fmaf(h.y, s_sc[u + 1], s_sh[u + 1]), 0.f);
            h.z = fmaxf(fmaf(h.z, s_sc[u + 2], s_sh[u + 2]), 0.f);
            h.w = fmaxf(fmaf(h.w, s_sc[u + 3], s_sh[u + 3]), 0.f);
            ((float4*)(s_hb + p * HB_S))[c4] = h;
        }
        __syncthreads();

        // partial column max
        if (t < 128) {
            int ch = t & 63, half = t >> 6;
            int pb = half * 18, pe = half ? PP : 18;
            float m = -3.4e38f;
            for (int p = pb; p < pe; p++) m = fmaxf(m, s_hb[p * HB_S + ch]);
            s_mm[half * 64 + ch] = m;
        }
        __syncthreads();

        if (t < C2) s_m2[t] = fmaxf(s_mm[t], s_mm[64 + t]);
        __syncthreads();

        // fold keep into s_hb; compute B (phys channel space)
        for (int i = t; i < PP * C2; i += T2) {
            int p = i >> 6, u = i & 63;
            s_hb[p * HB_S + u] *= s_keep[p];
        }
        if (t < 128) {
            float bsum = 0.f;
            #pragma unroll 8
            for (int k = 0; k < 64; k++)
                bsum = fmaf(s_m2[k], s_wd[(64 + k) * A2C + t], bsum);
            s_B[t] = bsum;
        }
        __syncthreads();

        // GEMM (k<64): 16 outputs x 2 points; 4 LDS.128 + 2 LDS.32 per k
        ull acc0[8], acc1[8];
        #pragma unroll
        for (int j = 0; j < 8; j++) {
            ull b = ((const ull*)bd)[8 * ogi + j];
            acc0[j] = b; acc1[j] = b;
        }
        const float* hb0 = s_hb + p0 * HB_S;
        const float* hb1 = s_hb + p1 * HB_S;

        #pragma unroll 4
        for (int k = 0; k < 64; k++) {
            const ulonglong2* wk = (const ulonglong2*)(s_wd + k * A2C);
            float a0f = hb0[k], a1f = hb1[k];
            ull a0 = pack2(a0f, a0f), a1 = pack2(a1f, a1f);
            #pragma unroll
            for (int q = 0; q < 4; q++) {
                ulonglong2 w = wk[8 * q + ogi];
                fma2(acc0[2 * q],     a0, w.x);
                fma2(acc0[2 * q + 1], a0, w.y);
                fma2(acc1[2 * q],     a1, w.x);
                fma2(acc1[2 * q + 1], a1, w.y);
            }
        }

        // epilogue: + keep*B
        {
            float kp0 = s_keep[p0], kp1 = s_keep[p1];
            ull kpp0 = pack2(kp0, kp0), kpp1 = pack2(kp1, kp1);
            const ulonglong2* sB2 = (const ulonglong2*)s_B;
            #pragma unroll
            for (int q = 0; q < 4; q++) {
                ulonglong2 Bq = sB2[8 * q + ogi];
                fma2(acc0[2 * q],     Bq.x, kpp0);
                fma2(acc0[2 * q + 1], Bq.y, kpp0);
                fma2(acc1[2 * q],     Bq.x, kpp1);
                fma2(acc1[2 * q + 1], Bq.y, kpp1);
            }
        }

        // store h3 tile (phys layout), real points only
        if (p0 < PP) {
            ulonglong2* dst = (ulonglong2*)(s_h3 + p0 * H3_S);
            #pragma unroll
            for (int q = 0; q < 4; q++) {
                ulonglong2 val; val.x = acc0[2 * q]; val.y = acc0[2 * q + 1];
                dst[8 * q + ogi] = val;
            }
        }
        if (p1 < PP) {
            ulonglong2* dst = (ulonglong2*)(s_h3 + p1 * H3_S);
            #pragma unroll
            for (int q = 0; q < 4; q++) {
                ulonglong2 val; val.x = acc1[2 * q]; val.y = acc1[2 * q + 1];
                dst[8 * q + ogi] = val;
            }
        }
        __syncthreads();

        // stats over 35 points (phys column t -> true channel o)
        if (t < C3) {
            float S = 0.f, Q = 0.f, MX = -3.4e38f, MN = 3.4e38f;
            #pragma unroll 7
            for (int p = 0; p < PP; p++) {
                float val = s_h3[p * H3_S + t];
                S += val; Q = fmaf(val, val, Q);
                MX = fmaxf(MX, val); MN = fminf(MN, val);
            }
            int r = t & 31;
            int o = (r >> 2) * 16 + (t >> 5) * 4 + (r & 3);
            g_max3[(size_t)v * C3 + o] = MX;
            g_min3[(size_t)v * C3 + o] = MN;
            int b = v & (NBUCK - 1);
            atomicAdd(&g_sumB[b][C1 + C2 + o], (double)S);
            atomicAdd(&g_sqB [b][C1 + C2 + o], (double)Q);
        }
        __syncthreads();
    }
}

// ---------------- pass 4: BN3 + relu + max (via max/min) + scatter-add ------------
__global__ void k_scatter(const int* __restrict__ coord, float* __restrict__ out, int V) {
    int v = blockIdx.x;
    if (v >= V) return;
    int u = threadIdx.x;
    float sc = g_scale[C1 + C2 + u];
    float sh = g_shift[C1 + C2 + u];
    float h  = (sc >= 0.0f) ? g_max3[(size_t)v * C3 + u] : g_min3[(size_t)v * C3 + u];
    float val = fmaxf(fmaf(h, sc, sh), 0.0f);
    int cz = coord[v * 3 + 0];
    int cy = coord[v * 3 + 1];
    int cx = coord[v * 3 + 2];
    size_t off = (size_t)u * (DD * HH * WWG) + (size_t)cz * (HH * WWG) + (size_t)cy * WWG + cx;
    atomicAdd(out + off, val);
}

// ---------------- launch -----------------------------------------------------------
extern "C" void kernel_launch(void* const* d_in, const int* in_sizes, int n_in,
                              void* d_out, int out_size) {
    const float* x     = (const float*)d_in[0];
    const int*   coord = (const int*)  d_in[1];
    const float* W1 = (const float*)d_in[2];
    const float* b1 = (const float*)d_in[3];
    const float* g1 = (const float*)d_in[4];
    const float* be1= (const float*)d_in[5];
    const float* W2 = (const float*)d_in[6];
    const float* b2 = (const float*)d_in[7];
    const float* g2 = (const float*)d_in[8];
    const float* be2= (const float*)d_in[9];
    const float* Wd = (const float*)d_in[10];
    const float* bd = (const float*)d_in[11];
    const float* gd = (const float*)d_in[12];
    const float* bed= (const float*)d_in[13];

    int V = in_sizes[1] / 3;
    if (V > VMAX) V = VMAX;
    double invN = 1.0 / ((double)V * PP);

    cudaFuncSetAttribute(k_vfe2, cudaFuncAttributeMaxDynamicSharedMemorySize, SM2_BYTES);

    cudaMemsetAsync(d_out, 0, (size_t)out_size * sizeof(float), 0);
    k_zero_stats<<<32, 256>>>();
    k_stats1<<<592, 256>>>(x, W1, b1, V);
    k_finalize<<<1, 256>>>(g1, be1, 0, C1, invN);
    k_vfe1<<<V, 128>>>(x, W1, b1, W2, b2, V);
    k_finalize<<<1, 256>>>(g2, be2, C1, C2, invN);
    k_vfe2<<<GRID2, T2, SM2_BYTES>>>((const float4*)Wd, bd, V);
    k_finalize<<<1, 256>>>(gd, bed, C1 + C2, C3, invN);
    k_scatter<<<V, 128>>>(coord, (float*)d_out, V);
}